// round 4
// baseline (speedup 1.0000x reference)
#include <cuda_runtime.h>
#include <cuda_bf16.h>
#include <math.h>

// Problem constants
#define BATCH 4
#define HH 56
#define WW 56
#define CC 256
#define NHEAD 8
#define HD 32
#define KS 7
#define PADR 3
#define M_TOTAL (BATCH * HH * WW)   // 12544
#define QKV_N (3 * CC)              // 768

// Scratch (device globals: allocation-free rule)
__device__ float g_qkv[M_TOTAL * QKV_N];   // [pix][3*256] : q|k|v, q pre-scaled
__device__ float g_attn[M_TOTAL * CC];     // attention output (tf32-rounded)
__device__ float g_xa[M_TOTAL * CC];       // x, tf32-rounded
__device__ float g_wq[CC * QKV_N];         // w_qkv, tf32-rounded
__device__ float g_wp[CC * CC];            // w_proj, tf32-rounded

__device__ __forceinline__ unsigned f2tf32(float x) {
    unsigned r;
    asm("cvt.rna.tf32.f32 %0, %1;" : "=r"(r) : "f"(x));
    return r;
}

// ---------------------------------------------------------------------------
// Prep: RNA-round fp32 -> tf32-in-fp32 (one-time, removes cvt from GEMM loop)
// ---------------------------------------------------------------------------
__global__ void tf32_round_kernel(const float4* __restrict__ in,
                                  float4* __restrict__ out, int n4)
{
    const int i = blockIdx.x * 256 + threadIdx.x;
    if (i < n4) {
        float4 v = in[i];
        v.x = __uint_as_float(f2tf32(v.x));
        v.y = __uint_as_float(f2tf32(v.y));
        v.z = __uint_as_float(f2tf32(v.z));
        v.w = __uint_as_float(f2tf32(v.w));
        out[i] = v;
    }
}

// ---------------------------------------------------------------------------
// TF32 tensor-core GEMM: C[M,N] = A[M,K] @ B[K,N] + bias[N], scaled cols.
// Inputs pre-rounded to tf32. Block 128x64x32, 256 thr = 8 warps (4Mx2N),
// warp tile 32x32, mma.m16n8k8. k%4-plane smem layout, PITCH 12 ->
// LDS.128 fragment loads over s-step pairs, all conflict-free.
// ---------------------------------------------------------------------------
#define BM 128
#define BN 64
#define BK 32
#define PITCH 12
#define APLANE (BM * PITCH + 8)       // 1544 (%8 chunks stagger = 2)
#define BPLANE (BN * PITCH + 8)       // 776
#define STAGE_FLOATS (4 * APLANE + 4 * BPLANE)   // 9280
#define GEMM_SMEM_BYTES (2 * STAGE_FLOATS * 4)   // 74240

__device__ __forceinline__ void mma_tf32(float4& d,
    float a0, float a1, float a2, float a3, float b0, float b1)
{
    asm volatile(
        "mma.sync.aligned.m16n8k8.row.col.f32.tf32.tf32.f32 "
        "{%0,%1,%2,%3},{%4,%5,%6,%7},{%8,%9},{%0,%1,%2,%3};\n"
        : "+f"(d.x), "+f"(d.y), "+f"(d.z), "+f"(d.w)
        : "r"(__float_as_uint(a0)), "r"(__float_as_uint(a1)),
          "r"(__float_as_uint(a2)), "r"(__float_as_uint(a3)),
          "r"(__float_as_uint(b0)), "r"(__float_as_uint(b1)));
}

__global__ __launch_bounds__(256, 3) void tgemm_bias(
    const float* __restrict__ A, const float* __restrict__ B,
    const float* __restrict__ bias, float* __restrict__ C,
    int N, int K, int scaleCols, float scale)
{
    extern __shared__ float sm[];
    const int tid  = threadIdx.x;
    const int wid  = tid >> 5;
    const int lane = tid & 31;
    const int warp_m = wid & 3;
    const int warp_n = wid >> 2;
    const int c  = lane & 3;           // k%4 plane
    const int qr = lane >> 2;          // quad row 0..7
    const int bm = blockIdx.y << 7;
    const int bn = blockIdx.x << 6;

    // A global: thread loads 4 float4 (rows am+32e, k-quad akq)
    const int am  = tid >> 3;          // 0..31
    const int akq = tid & 7;
    const float* Ag = A + (size_t)(bm + am) * K + akq * 4;

    // B global: thread loads 8 scalars col bnn, k-rows br0+4e (same plane br0)
    const int bnn = tid & 63;
    const int br0 = tid >> 6;          // 0..3
    const float* Bg = B + bn + bnn;

    // smem bases
    float* aSt = sm + am * PITCH + akq;                     // + j*APLANE + e*32*PITCH
    float* bSt = sm + 4 * APLANE + br0 * BPLANE + bnn * PITCH;
    const float* aFr = sm + c * APLANE + (warp_m * 32) * PITCH;
    const float* bFr = sm + 4 * APLANE + c * BPLANE + (warp_n * 32) * PITCH;

    float acc[2][4][4];
    #pragma unroll
    for (int mt = 0; mt < 2; ++mt)
        #pragma unroll
        for (int nt = 0; nt < 4; ++nt)
            #pragma unroll
            for (int i = 0; i < 4; ++i) acc[mt][nt][i] = 0.f;

    const int ntiles = K >> 5;

    // ---- prologue: stage 0 ----
    {
        float4 pa[4];
        float pb[8];
        #pragma unroll
        for (int e = 0; e < 4; ++e)
            pa[e] = *(const float4*)(Ag + (size_t)e * 32 * K);
        #pragma unroll
        for (int e = 0; e < 8; ++e)
            pb[e] = Bg[(size_t)(br0 + 4 * e) * N];
        #pragma unroll
        for (int e = 0; e < 4; ++e) {
            float* p = aSt + e * 32 * PITCH;
            p[0*APLANE] = pa[e].x; p[1*APLANE] = pa[e].y;
            p[2*APLANE] = pa[e].z; p[3*APLANE] = pa[e].w;
        }
        *(float4*)bSt       = make_float4(pb[0], pb[1], pb[2], pb[3]);
        *(float4*)(bSt + 4) = make_float4(pb[4], pb[5], pb[6], pb[7]);
    }
    __syncthreads();

    for (int t = 0; t < ntiles; ++t) {
        float4 pa[4];
        float pb[8];
        if (t + 1 < ntiles) {
            #pragma unroll
            for (int e = 0; e < 4; ++e)
                pa[e] = *(const float4*)(Ag + (size_t)e * 32 * K + (t + 1) * BK);
            #pragma unroll
            for (int e = 0; e < 8; ++e)
                pb[e] = Bg[(size_t)((t + 1) * BK + br0 + 4 * e) * N];
        }

        const float* as = aFr + (t & 1) * STAGE_FLOATS;
        const float* bs = bFr + (t & 1) * STAGE_FLOATS;
        #pragma unroll
        for (int s2 = 0; s2 < 2; ++s2) {
            float4 aL[2], aH[2], bf[4];
            #pragma unroll
            for (int mt = 0; mt < 2; ++mt) {
                aL[mt] = *(const float4*)(as + (mt*16 + qr) * PITCH + 4*s2);
                aH[mt] = *(const float4*)(as + (mt*16 + qr + 8) * PITCH + 4*s2);
            }
            #pragma unroll
            for (int nt = 0; nt < 4; ++nt)
                bf[nt] = *(const float4*)(bs + (nt*8 + qr) * PITCH + 4*s2);
            // s = 2*s2 (even)
            #pragma unroll
            for (int mt = 0; mt < 2; ++mt)
                #pragma unroll
                for (int nt = 0; nt < 4; ++nt)
                    mma_tf32(*(float4*)acc[mt][nt],
                             aL[mt].x, aH[mt].x, aL[mt].y, aH[mt].y,
                             bf[nt].x, bf[nt].y);
            // s = 2*s2+1 (odd)
            #pragma unroll
            for (int mt = 0; mt < 2; ++mt)
                #pragma unroll
                for (int nt = 0; nt < 4; ++nt)
                    mma_tf32(*(float4*)acc[mt][nt],
                             aL[mt].z, aH[mt].z, aL[mt].w, aH[mt].w,
                             bf[nt].z, bf[nt].w);
        }

        if (t + 1 < ntiles) {
            float* naSt = aSt + ((t + 1) & 1) * STAGE_FLOATS;
            float* nbSt = bSt + ((t + 1) & 1) * STAGE_FLOATS;
            #pragma unroll
            for (int e = 0; e < 4; ++e) {
                float* p = naSt + e * 32 * PITCH;
                p[0*APLANE] = pa[e].x; p[1*APLANE] = pa[e].y;
                p[2*APLANE] = pa[e].z; p[3*APLANE] = pa[e].w;
            }
            *(float4*)nbSt       = make_float4(pb[0], pb[1], pb[2], pb[3]);
            *(float4*)(nbSt + 4) = make_float4(pb[4], pb[5], pb[6], pb[7]);
        }
        __syncthreads();
    }

    // ---- epilogue: bias + optional scale ----
    const float sc = (bn < scaleCols) ? scale : 1.f;
    #pragma unroll
    for (int nt = 0; nt < 4; ++nt) {
        const int gn = bn + warp_n * 32 + nt * 8 + 2 * c;
        const float2 bz = *(const float2*)&bias[gn];
        #pragma unroll
        for (int mt = 0; mt < 2; ++mt) {
            const int gm = bm + warp_m * 32 + mt * 16 + qr;
            float2 r0, r1;
            r0.x = (acc[mt][nt][0] + bz.x) * sc;
            r0.y = (acc[mt][nt][1] + bz.y) * sc;
            r1.x = (acc[mt][nt][2] + bz.x) * sc;
            r1.y = (acc[mt][nt][3] + bz.y) * sc;
            *(float2*)&C[(size_t)gm * N + gn] = r0;
            *(float2*)&C[(size_t)(gm + 8) * N + gn] = r1;
        }
    }
}

// ---------------------------------------------------------------------------
// Neighborhood attention (fp32 math, in-register softmax). Output is
// tf32-RNA-rounded so the proj GEMM needs no conversion.
// ---------------------------------------------------------------------------
#define TQ 8
#define WIN 14
#define KP 36            // k/v smem row pitch (floats)
#define SP 53            // score row pitch (floats)
#define ATTN_SMEM_FLOATS (2 * WIN * WIN * KP + 64 * SP + 52)
#define ATTN_SMEM_BYTES (ATTN_SMEM_FLOATS * 4)

__global__ __launch_bounds__(256) void na2d_attn(
    const float* __restrict__ qkv, const float* __restrict__ rpb,
    float* __restrict__ out)
{
    extern __shared__ float sm[];
    float* ks_  = sm;                          // [196][KP]
    float* vs_  = sm + WIN * WIN * KP;         // [196][KP]
    float* sc   = sm + 2 * WIN * WIN * KP;     // [64][SP]
    float* rpbs = sc + 64 * SP;                // [49]

    const int b    = blockIdx.z;
    const int head = blockIdx.y;
    const int tY   = blockIdx.x / 7;
    const int tX   = blockIdx.x - tY * 7;
    const int oy   = tY * TQ;
    const int ox   = tX * TQ;
    const int tid  = threadIdx.x;

    // --- load 14x14 k/v window (zero-padded) + rpb row ---
    if (tid < 49) rpbs[tid] = rpb[head * 49 + tid];
    for (int idx = tid; idx < WIN * WIN * 8; idx += 256) {
        const int row = idx >> 3;
        const int d4  = idx & 7;
        const int wy = row / WIN, wx = row - wy * WIN;
        const int gy = oy - PADR + wy, gx = ox - PADR + wx;
        float4 kv = make_float4(0.f, 0.f, 0.f, 0.f);
        float4 vv = make_float4(0.f, 0.f, 0.f, 0.f);
        if (gy >= 0 && gy < HH && gx >= 0 && gx < WW) {
            const float* p = qkv + (size_t)(((b * HH + gy) * WW) + gx) * QKV_N
                           + head * HD + d4 * 4;
            kv = *(const float4*)(p + 256);
            vv = *(const float4*)(p + 512);
        }
        *(float4*)&ks_[row * KP + d4 * 4] = kv;
        *(float4*)&vs_[row * KP + d4 * 4] = vv;
    }

    // --- q into registers (4 threads per query share the same q) ---
    const int qi = tid >> 2;       // 0..63
    const int g  = tid & 3;        // 0..3
    const int qy = qi >> 3, qx = qi & 7;
    const size_t qpix = (size_t)((b * HH + oy + qy) * WW) + ox + qx;
    const float4* qp = (const float4*)(qkv + qpix * QKV_N + head * HD);
    float4 qv[8];
    #pragma unroll
    for (int cc = 0; cc < 8; ++cc) qv[cc] = qp[cc];

    __syncthreads();

    // --- phase 1: scores in registers ---
    float sv[13];
    #pragma unroll
    for (int u = 0; u < 13; ++u) {
        const int j = g + 4 * u;
        const bool act = (j < 49);
        const int jc = act ? j : 48;
        const int di = jc / 7, dj = jc - di * 7;
        const float4* kr = (const float4*)(ks_ + ((qy + di) * WIN + qx + dj) * KP);
        float s0 = 0.f, s1 = 0.f, s2 = 0.f, s3 = 0.f;
        #pragma unroll
        for (int cc = 0; cc < 8; cc += 2) {
            const float4 k0 = kr[cc], k1 = kr[cc + 1];
            s0 = fmaf(qv[cc].x, k0.x, s0);
            s1 = fmaf(qv[cc].y, k0.y, s1);
            s2 = fmaf(qv[cc].z, k0.z, s2);
            s3 = fmaf(qv[cc].w, k0.w, s3);
            s0 = fmaf(qv[cc+1].x, k1.x, s0);
            s1 = fmaf(qv[cc+1].y, k1.y, s1);
            s2 = fmaf(qv[cc+1].z, k1.z, s2);
            s3 = fmaf(qv[cc+1].w, k1.w, s3);
        }
        sv[u] = act ? ((s0 + s1) + (s2 + s3) + rpbs[jc]) : -1e30f;
    }

    // --- softmax across quad ---
    float m = sv[0];
    #pragma unroll
    for (int u = 1; u < 13; ++u) m = fmaxf(m, sv[u]);
    m = fmaxf(m, __shfl_xor_sync(0xffffffffu, m, 1));
    m = fmaxf(m, __shfl_xor_sync(0xffffffffu, m, 2));
    float ssum = 0.f;
    #pragma unroll
    for (int u = 0; u < 13; ++u) {
        const float e = __expf(sv[u] - m);
        sv[u] = e;
        ssum += e;
    }
    ssum += __shfl_xor_sync(0xffffffffu, ssum, 1);
    ssum += __shfl_xor_sync(0xffffffffu, ssum, 2);
    const float inv = 1.f / ssum;
    #pragma unroll
    for (int u = 0; u < 13; ++u) {
        const int j = g + 4 * u;
        if (j < 49) sc[qi * SP + j] = sv[u] * inv;
    }
    __syncthreads();

    // --- phase 3: AV ---
    float4 a0 = make_float4(0.f, 0.f, 0.f, 0.f);
    float4 a1 = make_float4(0.f, 0.f, 0.f, 0.f);
    int jj = 0;
    #pragma unroll
    for (int di = 0; di < 7; ++di) {
        #pragma unroll
        for (int dj = 0; dj < 7; ++dj) {
            const float w = sc[qi * SP + jj];
            const float4* vr = (const float4*)(vs_ + ((qy + di) * WIN + qx + dj) * KP + g * 8);
            const float4 v0 = vr[0], v1 = vr[1];
            a0.x = fmaf(w, v0.x, a0.x); a0.y = fmaf(w, v0.y, a0.y);
            a0.z = fmaf(w, v0.z, a0.z); a0.w = fmaf(w, v0.w, a0.w);
            a1.x = fmaf(w, v1.x, a1.x); a1.y = fmaf(w, v1.y, a1.y);
            a1.z = fmaf(w, v1.z, a1.z); a1.w = fmaf(w, v1.w, a1.w);
            ++jj;
        }
    }
    // tf32-RNA-round the attention output so proj GEMM consumes it directly
    a0.x = __uint_as_float(f2tf32(a0.x)); a0.y = __uint_as_float(f2tf32(a0.y));
    a0.z = __uint_as_float(f2tf32(a0.z)); a0.w = __uint_as_float(f2tf32(a0.w));
    a1.x = __uint_as_float(f2tf32(a1.x)); a1.y = __uint_as_float(f2tf32(a1.y));
    a1.z = __uint_as_float(f2tf32(a1.z)); a1.w = __uint_as_float(f2tf32(a1.w));
    float* op = out + qpix * CC + head * HD + g * 8;
    *(float4*)op = a0;
    *(float4*)(op + 4) = a1;
}

// ---------------------------------------------------------------------------
extern "C" void kernel_launch(void* const* d_in, const int* in_sizes, int n_in,
                              void* d_out, int out_size)
{
    (void)in_sizes; (void)n_in; (void)out_size;
    const float* x      = (const float*)d_in[0];
    const float* w_qkv  = (const float*)d_in[1];
    const float* b_qkv  = (const float*)d_in[2];
    const float* rpb    = (const float*)d_in[3];
    const float* w_proj = (const float*)d_in[4];
    const float* b_proj = (const float*)d_in[5];
    float* out = (float*)d_out;

    float *qkvb = nullptr, *attnb = nullptr, *xa = nullptr, *wq = nullptr, *wp = nullptr;
    cudaGetSymbolAddress((void**)&qkvb, g_qkv);
    cudaGetSymbolAddress((void**)&attnb, g_attn);
    cudaGetSymbolAddress((void**)&xa, g_xa);
    cudaGetSymbolAddress((void**)&wq, g_wq);
    cudaGetSymbolAddress((void**)&wp, g_wp);

    cudaFuncSetAttribute(tgemm_bias, cudaFuncAttributeMaxDynamicSharedMemorySize,
                         GEMM_SMEM_BYTES);
    cudaFuncSetAttribute(na2d_attn, cudaFuncAttributeMaxDynamicSharedMemorySize,
                         ATTN_SMEM_BYTES);

    const float qscale = 0.17677669529663689f; // 32^-0.5

    // 0) one-time tf32 rounding of GEMM inputs
    {
        const int nx = M_TOTAL * CC / 4;
        tf32_round_kernel<<<(nx + 255) / 256, 256>>>((const float4*)x, (float4*)xa, nx);
        const int nq = CC * QKV_N / 4;
        tf32_round_kernel<<<(nq + 255) / 256, 256>>>((const float4*)w_qkv, (float4*)wq, nq);
        const int np = CC * CC / 4;
        tf32_round_kernel<<<(np + 255) / 256, 256>>>((const float4*)w_proj, (float4*)wp, np);
    }

    // 1) qkv = x @ w_qkv + b_qkv  (q columns pre-scaled)
    tgemm_bias<<<dim3(QKV_N / 64, M_TOTAL / 128), 256, GEMM_SMEM_BYTES>>>(
        xa, wq, b_qkv, qkvb, QKV_N, CC, 256, qscale);

    // 2) neighborhood attention
    na2d_attn<<<dim3(49, NHEAD, BATCH), 256, ATTN_SMEM_BYTES>>>(qkvb, rpb, attnb);

    // 3) out = attn @ w_proj + b_proj
    tgemm_bias<<<dim3(CC / 64, M_TOTAL / 128), 256, GEMM_SMEM_BYTES>>>(
        attnb, wp, b_proj, out, CC, CC, 0, 1.f);
}

// round 6
// speedup vs baseline: 1.1802x; 1.1802x over previous
#include <cuda_runtime.h>
#include <cuda_bf16.h>
#include <math.h>

// Problem constants
#define BATCH 4
#define HH 56
#define WW 56
#define CC 256
#define NHEAD 8
#define HD 32
#define KS 7
#define PADR 3
#define M_TOTAL (BATCH * HH * WW)   // 12544
#define QKV_N (3 * CC)              // 768

// Scratch (device globals: allocation-free rule)
__device__ float g_qkv[M_TOTAL * QKV_N];   // [pix][3*256] : q|k|v, q pre-scaled
__device__ float g_attn[M_TOTAL * CC];     // attention output (tf32-rounded)
__device__ float g_xa[M_TOTAL * CC];       // x, tf32-rounded
__device__ float g_wq[CC * QKV_N];         // w_qkv, tf32-rounded
__device__ float g_wp[CC * CC];            // w_proj, tf32-rounded

__device__ __forceinline__ unsigned f2tf32(float x) {
    unsigned r;
    asm("cvt.rna.tf32.f32 %0, %1;" : "=r"(r) : "f"(x));
    return r;
}

// ---------------------------------------------------------------------------
// Prep: RNA-round fp32 -> tf32-in-fp32 (one-time; GEMM loop has zero cvt)
// ---------------------------------------------------------------------------
__global__ void tf32_round_kernel(const float4* __restrict__ in,
                                  float4* __restrict__ out, int n4)
{
    const int i = blockIdx.x * 256 + threadIdx.x;
    if (i < n4) {
        float4 v = in[i];
        v.x = __uint_as_float(f2tf32(v.x));
        v.y = __uint_as_float(f2tf32(v.y));
        v.z = __uint_as_float(f2tf32(v.z));
        v.w = __uint_as_float(f2tf32(v.w));
        out[i] = v;
    }
}

// ---------------------------------------------------------------------------
// TF32 tensor-core GEMM (pre-rounded inputs): C = A @ B + bias, scaled cols.
// Block tile 128x64x32, 256 thr = 8 warps (4Mx2N), warp tile 32x32,
// mma.m16n8k8. k%4-plane smem layout, PITCH 10 (62KB total, 3 blocks/SM).
// Identical layout to the round-3 kernel; only the cvts are gone.
// ---------------------------------------------------------------------------
#define BM 128
#define BN 64
#define BK 32
#define PITCH 10
#define APLANE (BM * PITCH + 8)       // 1288
#define BPLANE (BN * PITCH + 8)       // 648
#define STAGE_FLOATS (4 * APLANE + 4 * BPLANE)   // 7744
#define GEMM_SMEM_BYTES (2 * STAGE_FLOATS * 4)   // 61952

__device__ __forceinline__ void mma_tf32(float4& d,
    float a0, float a1, float a2, float a3, float b0, float b1)
{
    asm volatile(
        "mma.sync.aligned.m16n8k8.row.col.f32.tf32.tf32.f32 "
        "{%0,%1,%2,%3},{%4,%5,%6,%7},{%8,%9},{%0,%1,%2,%3};\n"
        : "+f"(d.x), "+f"(d.y), "+f"(d.z), "+f"(d.w)
        : "r"(__float_as_uint(a0)), "r"(__float_as_uint(a1)),
          "r"(__float_as_uint(a2)), "r"(__float_as_uint(a3)),
          "r"(__float_as_uint(b0)), "r"(__float_as_uint(b1)));
}

__global__ __launch_bounds__(256, 3) void tgemm_bias(
    const float* __restrict__ A, const float* __restrict__ B,
    const float* __restrict__ bias, float* __restrict__ C,
    int N, int K, int scaleCols, float scale)
{
    extern __shared__ float sm[];
    const int tid  = threadIdx.x;
    const int wid  = tid >> 5;
    const int lane = tid & 31;
    const int warp_m = wid & 3;
    const int warp_n = wid >> 2;
    const int c  = lane & 3;           // k%4 plane
    const int qr = lane >> 2;          // quad row 0..7
    const int bm = blockIdx.y << 7;
    const int bn = blockIdx.x << 6;

    const int am  = tid >> 3;          // 0..31 (rows am+32e)
    const int akq = tid & 7;
    const float* Ag = A + (size_t)(bm + am) * K + akq * 4;

    const int bnn = tid & 63;
    const int br0 = tid >> 6;          // 0..3
    const float* Bg = B + bn + bnn;

    float acc[2][4][4];
    #pragma unroll
    for (int mt = 0; mt < 2; ++mt)
        #pragma unroll
        for (int nt = 0; nt < 4; ++nt)
            #pragma unroll
            for (int i = 0; i < 4; ++i) acc[mt][nt][i] = 0.f;

    const int ntiles = K >> 5;

    // ---- prologue: stage 0 ----
    {
        float4 pa[4];
        float pb[8];
        #pragma unroll
        for (int e = 0; e < 4; ++e)
            pa[e] = *(const float4*)(Ag + (size_t)e * 32 * K);
        #pragma unroll
        for (int e = 0; e < 8; ++e)
            pb[e] = Bg[(size_t)(br0 + 4 * e) * N];

        float* as = sm;
        float* bs = sm + 4 * APLANE;
        #pragma unroll
        for (int e = 0; e < 4; ++e) {
            const int m = am + 32 * e;
            as[0*APLANE + m*PITCH + akq] = pa[e].x;
            as[1*APLANE + m*PITCH + akq] = pa[e].y;
            as[2*APLANE + m*PITCH + akq] = pa[e].z;
            as[3*APLANE + m*PITCH + akq] = pa[e].w;
        }
        #pragma unroll
        for (int e = 0; e < 8; ++e)
            bs[br0*BPLANE + bnn*PITCH + e] = pb[e];
    }
    __syncthreads();

    for (int t = 0; t < ntiles; ++t) {
        float4 pa[4];
        float pb[8];
        if (t + 1 < ntiles) {
            #pragma unroll
            for (int e = 0; e < 4; ++e)
                pa[e] = *(const float4*)(Ag + (size_t)e * 32 * K + (t + 1) * BK);
            #pragma unroll
            for (int e = 0; e < 8; ++e)
                pb[e] = Bg[(size_t)((t + 1) * BK + br0 + 4 * e) * N];
        }

        const float* as = sm + (t & 1) * STAGE_FLOATS;
        const float* bs = as + 4 * APLANE;
        #pragma unroll
        for (int s = 0; s < 4; ++s) {
            float2 af[2][2];
            #pragma unroll
            for (int mt = 0; mt < 2; ++mt) {
                const int r0 = warp_m * 32 + mt * 16 + qr;
                af[mt][0] = *(const float2*)(as + c*APLANE + r0*PITCH + 2*s);
                af[mt][1] = *(const float2*)(as + c*APLANE + (r0+8)*PITCH + 2*s);
            }
            float2 bf[4];
            #pragma unroll
            for (int nt = 0; nt < 4; ++nt) {
                const int cn = warp_n * 32 + nt * 8 + qr;
                bf[nt] = *(const float2*)(bs + c*BPLANE + cn*PITCH + 2*s);
            }
            #pragma unroll
            for (int mt = 0; mt < 2; ++mt)
                #pragma unroll
                for (int nt = 0; nt < 4; ++nt)
                    mma_tf32(*(float4*)acc[mt][nt],
                             af[mt][0].x, af[mt][1].x,
                             af[mt][0].y, af[mt][1].y,
                             bf[nt].x, bf[nt].y);
        }

        if (t + 1 < ntiles) {
            float* nas = sm + ((t + 1) & 1) * STAGE_FLOATS;
            float* nbs = nas + 4 * APLANE;
            #pragma unroll
            for (int e = 0; e < 4; ++e) {
                const int m = am + 32 * e;
                nas[0*APLANE + m*PITCH + akq] = pa[e].x;
                nas[1*APLANE + m*PITCH + akq] = pa[e].y;
                nas[2*APLANE + m*PITCH + akq] = pa[e].z;
                nas[3*APLANE + m*PITCH + akq] = pa[e].w;
            }
            #pragma unroll
            for (int e = 0; e < 8; ++e)
                nbs[br0*BPLANE + bnn*PITCH + e] = pb[e];
        }
        __syncthreads();
    }

    // ---- epilogue: bias + optional scale ----
    const float sc = (bn < scaleCols) ? scale : 1.f;
    #pragma unroll
    for (int nt = 0; nt < 4; ++nt) {
        const int gn = bn + warp_n * 32 + nt * 8 + 2 * c;
        const float2 bz = *(const float2*)&bias[gn];
        #pragma unroll
        for (int mt = 0; mt < 2; ++mt) {
            const int gm = bm + warp_m * 32 + mt * 16 + qr;
            float2 r0, r1;
            r0.x = (acc[mt][nt][0] + bz.x) * sc;
            r0.y = (acc[mt][nt][1] + bz.y) * sc;
            r1.x = (acc[mt][nt][2] + bz.x) * sc;
            r1.y = (acc[mt][nt][3] + bz.y) * sc;
            *(float2*)&C[(size_t)gm * N + gn] = r0;
            *(float2*)&C[(size_t)(gm + 8) * N + gn] = r1;
        }
    }
}

// ---------------------------------------------------------------------------
// Neighborhood attention. One block = (batch, head, 8x8 query tile).
// Scores live entirely in registers: quad-shfl softmax, and the AV loop
// broadcasts each normalized weight via one shfl (no score smem, no second
// barrier). Output tf32-RNA-rounded for the proj GEMM.
// ---------------------------------------------------------------------------
#define TQ 8
#define WIN 14
#define KP 36            // k/v smem row pitch (floats)
#define ATTN_SMEM_FLOATS (2 * WIN * WIN * KP + 52)
#define ATTN_SMEM_BYTES (ATTN_SMEM_FLOATS * 4)

__global__ __launch_bounds__(256) void na2d_attn(
    const float* __restrict__ qkv, const float* __restrict__ rpb,
    float* __restrict__ out)
{
    extern __shared__ float sm[];
    float* ks_  = sm;                          // [196][KP]
    float* vs_  = sm + WIN * WIN * KP;         // [196][KP]
    float* rpbs = sm + 2 * WIN * WIN * KP;     // [49]

    const int b    = blockIdx.z;
    const int head = blockIdx.y;
    const int tY   = blockIdx.x / 7;
    const int tX   = blockIdx.x - tY * 7;
    const int oy   = tY * TQ;
    const int ox   = tX * TQ;
    const int tid  = threadIdx.x;

    // --- load 14x14 k/v window + rpb row ---
    if (tid < 49) rpbs[tid] = rpb[head * 49 + tid];
    const bool interior = (tY >= 1) && (tY <= 5) && (tX >= 1) && (tX <= 5);
    if (interior) {
        #pragma unroll 1
        for (int idx = tid; idx < WIN * WIN * 8; idx += 256) {
            const int row = idx >> 3;
            const int d4  = idx & 7;
            const int wy = row / WIN, wx = row - wy * WIN;
            const int gy = oy - PADR + wy, gx = ox - PADR + wx;
            const float* p = qkv + (size_t)(((b * HH + gy) * WW) + gx) * QKV_N
                           + head * HD + d4 * 4;
            *(float4*)&ks_[row * KP + d4 * 4] = *(const float4*)(p + 256);
            *(float4*)&vs_[row * KP + d4 * 4] = *(const float4*)(p + 512);
        }
    } else {
        #pragma unroll 1
        for (int idx = tid; idx < WIN * WIN * 8; idx += 256) {
            const int row = idx >> 3;
            const int d4  = idx & 7;
            const int wy = row / WIN, wx = row - wy * WIN;
            const int gy = oy - PADR + wy, gx = ox - PADR + wx;
            float4 kv = make_float4(0.f, 0.f, 0.f, 0.f);
            float4 vv = make_float4(0.f, 0.f, 0.f, 0.f);
            if (gy >= 0 && gy < HH && gx >= 0 && gx < WW) {
                const float* p = qkv + (size_t)(((b * HH + gy) * WW) + gx) * QKV_N
                               + head * HD + d4 * 4;
                kv = *(const float4*)(p + 256);
                vv = *(const float4*)(p + 512);
            }
            *(float4*)&ks_[row * KP + d4 * 4] = kv;
            *(float4*)&vs_[row * KP + d4 * 4] = vv;
        }
    }

    // --- q into registers (4 threads per query share the same q) ---
    const int qi = tid >> 2;       // 0..63
    const int g  = tid & 3;        // 0..3
    const int qy = qi >> 3, qx = qi & 7;
    const size_t qpix = (size_t)((b * HH + oy + qy) * WW) + ox + qx;
    const float4* qp = (const float4*)(qkv + qpix * QKV_N + head * HD);
    float4 qv[8];
    #pragma unroll
    for (int cc = 0; cc < 8; ++cc) qv[cc] = qp[cc];

    __syncthreads();

    // --- phase 1: scores in registers (thread owns j = g + 4u) ---
    float sv[13];
    #pragma unroll
    for (int u = 0; u < 13; ++u) {
        const int j = g + 4 * u;
        const bool act = (j < 49);
        const int jc = act ? j : 48;
        const int di = jc / 7, dj = jc - di * 7;
        const float4* kr = (const float4*)(ks_ + ((qy + di) * WIN + qx + dj) * KP);
        float s0 = 0.f, s1 = 0.f, s2 = 0.f, s3 = 0.f;
        #pragma unroll
        for (int cc = 0; cc < 8; cc += 2) {
            const float4 k0 = kr[cc], k1 = kr[cc + 1];
            s0 = fmaf(qv[cc].x, k0.x, s0);
            s1 = fmaf(qv[cc].y, k0.y, s1);
            s2 = fmaf(qv[cc].z, k0.z, s2);
            s3 = fmaf(qv[cc].w, k0.w, s3);
            s0 = fmaf(qv[cc+1].x, k1.x, s0);
            s1 = fmaf(qv[cc+1].y, k1.y, s1);
            s2 = fmaf(qv[cc+1].z, k1.z, s2);
            s3 = fmaf(qv[cc+1].w, k1.w, s3);
        }
        sv[u] = act ? ((s0 + s1) + (s2 + s3) + rpbs[jc]) : -1e30f;
    }

    // --- softmax across quad; weights stay in registers ---
    float m = sv[0];
    #pragma unroll
    for (int u = 1; u < 13; ++u) m = fmaxf(m, sv[u]);
    m = fmaxf(m, __shfl_xor_sync(0xffffffffu, m, 1));
    m = fmaxf(m, __shfl_xor_sync(0xffffffffu, m, 2));
    float ssum = 0.f;
    #pragma unroll
    for (int u = 0; u < 13; ++u) {
        const float e = __expf(sv[u] - m);
        sv[u] = e;
        ssum += e;
    }
    ssum += __shfl_xor_sync(0xffffffffu, ssum, 1);
    ssum += __shfl_xor_sync(0xffffffffu, ssum, 2);
    const float inv = 1.f / ssum;
    #pragma unroll
    for (int u = 0; u < 13; ++u) sv[u] *= inv;

    // --- phase 3: AV. weight broadcast by quad shfl (no barrier needed) ---
    const int lanebase = (tid & 31) & ~3;
    float4 a0 = make_float4(0.f, 0.f, 0.f, 0.f);
    float4 a1 = make_float4(0.f, 0.f, 0.f, 0.f);
    #pragma unroll
    for (int di = 0; di < 7; ++di) {
        const float* vrow = vs_ + ((qy + di) * WIN + qx) * KP + g * 8;
        #pragma unroll
        for (int dj = 0; dj < 7; ++dj) {
            const int j = di * 7 + dj;
            const float w = __shfl_sync(0xffffffffu, sv[j >> 2],
                                        lanebase | (j & 3));
            const float4 v0 = *(const float4*)(vrow + dj * KP);
            const float4 v1 = *(const float4*)(vrow + dj * KP + 4);
            a0.x = fmaf(w, v0.x, a0.x); a0.y = fmaf(w, v0.y, a0.y);
            a0.z = fmaf(w, v0.z, a0.z); a0.w = fmaf(w, v0.w, a0.w);
            a1.x = fmaf(w, v1.x, a1.x); a1.y = fmaf(w, v1.y, a1.y);
            a1.z = fmaf(w, v1.z, a1.z); a1.w = fmaf(w, v1.w, a1.w);
        }
    }
    // tf32-RNA-round output so the proj GEMM consumes it directly
    a0.x = __uint_as_float(f2tf32(a0.x)); a0.y = __uint_as_float(f2tf32(a0.y));
    a0.z = __uint_as_float(f2tf32(a0.z)); a0.w = __uint_as_float(f2tf32(a0.w));
    a1.x = __uint_as_float(f2tf32(a1.x)); a1.y = __uint_as_float(f2tf32(a1.y));
    a1.z = __uint_as_float(f2tf32(a1.z)); a1.w = __uint_as_float(f2tf32(a1.w));
    float* op = out + qpix * CC + head * HD + g * 8;
    *(float4*)op = a0;
    *(float4*)(op + 4) = a1;
}

// ---------------------------------------------------------------------------
extern "C" void kernel_launch(void* const* d_in, const int* in_sizes, int n_in,
                              void* d_out, int out_size)
{
    (void)in_sizes; (void)n_in; (void)out_size;
    const float* x      = (const float*)d_in[0];
    const float* w_qkv  = (const float*)d_in[1];
    const float* b_qkv  = (const float*)d_in[2];
    const float* rpb    = (const float*)d_in[3];
    const float* w_proj = (const float*)d_in[4];
    const float* b_proj = (const float*)d_in[5];
    float* out = (float*)d_out;

    float *qkvb = nullptr, *attnb = nullptr, *xa = nullptr, *wq = nullptr, *wp = nullptr;
    cudaGetSymbolAddress((void**)&qkvb, g_qkv);
    cudaGetSymbolAddress((void**)&attnb, g_attn);
    cudaGetSymbolAddress((void**)&xa, g_xa);
    cudaGetSymbolAddress((void**)&wq, g_wq);
    cudaGetSymbolAddress((void**)&wp, g_wp);

    cudaFuncSetAttribute(tgemm_bias, cudaFuncAttributeMaxDynamicSharedMemorySize,
                         GEMM_SMEM_BYTES);
    cudaFuncSetAttribute(na2d_attn, cudaFuncAttributeMaxDynamicSharedMemorySize,
                         ATTN_SMEM_BYTES);

    const float qscale = 0.17677669529663689f; // 32^-0.5

    // 0) one-time tf32 rounding of GEMM inputs
    {
        const int nx = M_TOTAL * CC / 4;
        tf32_round_kernel<<<(nx + 255) / 256, 256>>>((const float4*)x, (float4*)xa, nx);
        const int nq = CC * QKV_N / 4;
        tf32_round_kernel<<<(nq + 255) / 256, 256>>>((const float4*)w_qkv, (float4*)wq, nq);
        const int np = CC * CC / 4;
        tf32_round_kernel<<<(np + 255) / 256, 256>>>((const float4*)w_proj, (float4*)wp, np);
    }

    // 1) qkv = x @ w_qkv + b_qkv  (q columns pre-scaled)
    tgemm_bias<<<dim3(QKV_N / 64, M_TOTAL / 128), 256, GEMM_SMEM_BYTES>>>(
        xa, wq, b_qkv, qkvb, QKV_N, CC, 256, qscale);

    // 2) neighborhood attention
    na2d_attn<<<dim3(49, NHEAD, BATCH), 256, ATTN_SMEM_BYTES>>>(qkvb, rpb, attnb);

    // 3) out = attn @ w_proj + b_proj
    tgemm_bias<<<dim3(CC / 64, M_TOTAL / 128), 256, GEMM_SMEM_BYTES>>>(
        attnb, wp, b_proj, out, CC, CC, 0, 1.f);
}

// round 8
// speedup vs baseline: 1.3114x; 1.1112x over previous
#include <cuda_runtime.h>
#include <cuda_bf16.h>
#include <math.h>
#include <stdint.h>

// Problem constants
#define BATCH 4
#define HH 56
#define WW 56
#define CC 256
#define NHEAD 8
#define HD 32
#define KS 7
#define PADR 3
#define M_TOTAL (BATCH * HH * WW)   // 12544
#define QKV_N (3 * CC)              // 768
#define GK 256                      // K of both GEMMs

// Scratch (device globals: allocation-free rule)
__device__ float g_qkv[M_TOTAL * QKV_N];    // [pix][768] q|k|v, q pre-scaled
__device__ float g_attnT[CC * M_TOTAL];     // attention out, TRANSPOSED [C][M], tf32
__device__ float g_xt[CC * M_TOTAL];        // x transposed [C][M], tf32
__device__ float g_wq[CC * QKV_N];          // w_qkv [K][N], tf32
__device__ float g_wp[CC * CC];             // w_proj [K][N], tf32

__device__ __forceinline__ unsigned f2tf32(float x) {
    unsigned r;
    asm("cvt.rna.tf32.f32 %0, %1;" : "=r"(r) : "f"(x));
    return r;
}
__device__ __forceinline__ uint32_t smem_u32(const void* p) {
    uint32_t a;
    asm("{ .reg .u64 t; cvta.to.shared.u64 t, %1; cvt.u32.u64 %0, t; }"
        : "=r"(a) : "l"(p));
    return a;
}
__device__ __forceinline__ void cp16(uint32_t dst, const void* src) {
    asm volatile("cp.async.cg.shared.global [%0], [%1], 16;\n"
                 :: "r"(dst), "l"(src));
}
#define CP_COMMIT() asm volatile("cp.async.commit_group;\n" ::: "memory")
#define CP_WAIT2()  asm volatile("cp.async.wait_group 2;\n" ::: "memory")

// ---------------------------------------------------------------------------
// Prep kernels
// ---------------------------------------------------------------------------
__global__ void tf32_round_kernel(const float4* __restrict__ in,
                                  float4* __restrict__ out, int n4)
{
    const int i = blockIdx.x * 256 + threadIdx.x;
    if (i < n4) {
        float4 v = in[i];
        v.x = __uint_as_float(f2tf32(v.x));
        v.y = __uint_as_float(f2tf32(v.y));
        v.z = __uint_as_float(f2tf32(v.z));
        v.w = __uint_as_float(f2tf32(v.w));
        out[i] = v;
    }
}

// x [M][C] -> xt [C][M], tf32-rounded
__global__ void transpose_round_x(const float* __restrict__ in,
                                  float* __restrict__ out)
{
    __shared__ float tile[32][33];
    const int m0 = blockIdx.x * 32;
    const int k0 = blockIdx.y * 32;
    for (int i = threadIdx.y; i < 32; i += 8)
        tile[i][threadIdx.x] = in[(size_t)(m0 + i) * CC + k0 + threadIdx.x];
    __syncthreads();
    for (int i = threadIdx.y; i < 32; i += 8)
        out[(size_t)(k0 + i) * M_TOTAL + m0 + threadIdx.x] =
            __uint_as_float(f2tf32(tile[threadIdx.x][i]));
}

// ---------------------------------------------------------------------------
// cp.async 4-stage TF32 GEMM.
// At [K=256][M] (tf32), B [K=256][N] (tf32).  C[M][N] = At^T @ B + bias.
// Block tile 128x64x32, 256 thr = 8 warps (4Mx2N), warp tile 32x32,
// mma.m16n8k8. Stage: A [32][136] + B [32][72] floats (8-bank row stagger
// -> conflict-free LDS.32 fragment loads). 4 stages = 104KB, 2 blocks/SM.
// Per tile each thread issues 4 cp.async for A (full 32x128 coverage) and
// 2 for B (full 32x64 coverage) -> 6 x 16B = whole 24KB tile.
// ---------------------------------------------------------------------------
#define NSTAGE 4
#define A_PITCH 136
#define B_PITCH 72
#define ASTG_B (32 * A_PITCH * 4)      // 17408
#define BSTG_B (32 * B_PITCH * 4)      // 9216
#define STG_B  (ASTG_B + BSTG_B)       // 26624
#define GEMM_SMEM (NSTAGE * STG_B)     // 106496

__device__ __forceinline__ void mma_tf32(float4& d,
    float a0, float a1, float a2, float a3, float b0, float b1)
{
    asm volatile(
        "mma.sync.aligned.m16n8k8.row.col.f32.tf32.tf32.f32 "
        "{%0,%1,%2,%3},{%4,%5,%6,%7},{%8,%9},{%0,%1,%2,%3};\n"
        : "+f"(d.x), "+f"(d.y), "+f"(d.z), "+f"(d.w)
        : "r"(__float_as_uint(a0)), "r"(__float_as_uint(a1)),
          "r"(__float_as_uint(a2)), "r"(__float_as_uint(a3)),
          "r"(__float_as_uint(b0)), "r"(__float_as_uint(b1)));
}

__global__ __launch_bounds__(256, 2) void tgemm_ca(
    const float* __restrict__ At, const float* __restrict__ B,
    const float* __restrict__ bias, float* __restrict__ C,
    int M, int N, int scaleCols, float scale)
{
    extern __shared__ float sm[];
    const uint32_t sb = smem_u32(sm);
    const int tid  = threadIdx.x;
    const int wid  = tid >> 5;
    const int lane = tid & 31;
    const int warp_m = wid & 3;
    const int warp_n = wid >> 2;
    const int t  = lane & 3;           // k within quad
    const int qr = lane >> 2;          // group row 0..7
    const int bm = blockIdx.y << 7;
    const int bn = blockIdx.x << 6;

    // load mapping: row r = tid>>3 (0..31), chunk col c = (tid&7) + 8e
    const int lr = tid >> 3;
    const int lc = tid & 7;
    const float* Asrc = At + (size_t)lr * M + bm + lc * 4;
    const float* Bsrc = B + (size_t)lr * N + bn + lc * 4;
    const uint32_t aOff = (uint32_t)(lr * A_PITCH + lc * 4) * 4u;
    const uint32_t bOff = (uint32_t)ASTG_B + (uint32_t)(lr * B_PITCH + lc * 4) * 4u;

    float acc[2][4][4];
    #pragma unroll
    for (int mt = 0; mt < 2; ++mt)
        #pragma unroll
        for (int nt = 0; nt < 4; ++nt)
            #pragma unroll
            for (int i = 0; i < 4; ++i) acc[mt][nt][i] = 0.f;

    // prologue: stages 0..2 <- tiles 0..2
    #pragma unroll
    for (int s = 0; s < NSTAGE - 1; ++s) {
        const uint32_t sd = sb + s * STG_B;
        #pragma unroll
        for (int e = 0; e < 4; ++e)
            cp16(sd + aOff + e * 128u, Asrc + (size_t)s * 32 * M + e * 32);
        #pragma unroll
        for (int e = 0; e < 2; ++e)
            cp16(sd + bOff + e * 128u, Bsrc + (size_t)s * 32 * N + e * 32);
        CP_COMMIT();
    }

    #pragma unroll 1
    for (int kt = 0; kt < 8; ++kt) {
        CP_WAIT2();          // tile kt resident
        __syncthreads();

        if (kt + 3 < 8) {
            const uint32_t sd = sb + ((kt + 3) & 3) * STG_B;
            #pragma unroll
            for (int e = 0; e < 4; ++e)
                cp16(sd + aOff + e * 128u, Asrc + (size_t)(kt + 3) * 32 * M + e * 32);
            #pragma unroll
            for (int e = 0; e < 2; ++e)
                cp16(sd + bOff + e * 128u, Bsrc + (size_t)(kt + 3) * 32 * N + e * 32);
        }
        CP_COMMIT();         // always commit (keeps wait_group arithmetic exact)

        const float* as = sm + (kt & 3) * (STG_B / 4) + warp_m * 32 + qr;
        const float* bs = sm + (kt & 3) * (STG_B / 4) + (ASTG_B / 4) + warp_n * 32 + qr;
        #pragma unroll
        for (int ss = 0; ss < 4; ++ss) {
            const float* ap = as + (ss * 8 + t) * A_PITCH;
            const float* bp = bs + (ss * 8 + t) * B_PITCH;
            float a0[2], a1[2], a2[2], a3[2];
            #pragma unroll
            for (int mt = 0; mt < 2; ++mt) {
                a0[mt] = ap[mt * 16];
                a1[mt] = ap[mt * 16 + 8];
                a2[mt] = ap[mt * 16 + 4 * A_PITCH];
                a3[mt] = ap[mt * 16 + 8 + 4 * A_PITCH];
            }
            float b0[4], b1[4];
            #pragma unroll
            for (int nt = 0; nt < 4; ++nt) {
                b0[nt] = bp[nt * 8];
                b1[nt] = bp[nt * 8 + 4 * B_PITCH];
            }
            #pragma unroll
            for (int mt = 0; mt < 2; ++mt)
                #pragma unroll
                for (int nt = 0; nt < 4; ++nt)
                    mma_tf32(*(float4*)acc[mt][nt],
                             a0[mt], a1[mt], a2[mt], a3[mt],
                             b0[nt], b1[nt]);
        }
    }

    // epilogue: c0 row=qr col=2t, c1 col=2t+1, c2/c3 row+8
    const float sc = (bn < scaleCols) ? scale : 1.f;
    #pragma unroll
    for (int nt = 0; nt < 4; ++nt) {
        const int gn = bn + warp_n * 32 + nt * 8 + 2 * t;
        const float2 bz = *(const float2*)&bias[gn];
        #pragma unroll
        for (int mt = 0; mt < 2; ++mt) {
            const int gm = bm + warp_m * 32 + mt * 16 + qr;
            float2 r0, r1;
            r0.x = (acc[mt][nt][0] + bz.x) * sc;
            r0.y = (acc[mt][nt][1] + bz.y) * sc;
            r1.x = (acc[mt][nt][2] + bz.x) * sc;
            r1.y = (acc[mt][nt][3] + bz.y) * sc;
            *(float2*)&C[(size_t)gm * N + gn] = r0;
            *(float2*)&C[(size_t)(gm + 8) * N + gn] = r1;
        }
    }
}

// ---------------------------------------------------------------------------
// Neighborhood attention. One block = (batch, head, 8x8 query tile).
// Register softmax + quad-shfl weight broadcast. Output written TRANSPOSED
// ([C][M], tf32-rounded) so the proj GEMM consumes it as its A directly.
// ---------------------------------------------------------------------------
#define TQ 8
#define WIN 14
#define KP 36
#define ATTN_SMEM_FLOATS (2 * WIN * WIN * KP + 52)
#define ATTN_SMEM_BYTES (ATTN_SMEM_FLOATS * 4)

__global__ __launch_bounds__(256) void na2d_attn(
    const float* __restrict__ qkv, const float* __restrict__ rpb,
    float* __restrict__ outT)
{
    extern __shared__ float sm[];
    float* ks_  = sm;
    float* vs_  = sm + WIN * WIN * KP;
    float* rpbs = sm + 2 * WIN * WIN * KP;

    const int b    = blockIdx.z;
    const int head = blockIdx.y;
    const int tY   = blockIdx.x / 7;
    const int tX   = blockIdx.x - tY * 7;
    const int oy   = tY * TQ;
    const int ox   = tX * TQ;
    const int tid  = threadIdx.x;

    if (tid < 49) rpbs[tid] = rpb[head * 49 + tid];
    const bool interior = (tY >= 1) && (tY <= 5) && (tX >= 1) && (tX <= 5);
    if (interior) {
        #pragma unroll 1
        for (int idx = tid; idx < WIN * WIN * 8; idx += 256) {
            const int row = idx >> 3;
            const int d4  = idx & 7;
            const int wy = row / WIN, wx = row - wy * WIN;
            const int gy = oy - PADR + wy, gx = ox - PADR + wx;
            const float* p = qkv + (size_t)(((b * HH + gy) * WW) + gx) * QKV_N
                           + head * HD + d4 * 4;
            *(float4*)&ks_[row * KP + d4 * 4] = *(const float4*)(p + 256);
            *(float4*)&vs_[row * KP + d4 * 4] = *(const float4*)(p + 512);
        }
    } else {
        #pragma unroll 1
        for (int idx = tid; idx < WIN * WIN * 8; idx += 256) {
            const int row = idx >> 3;
            const int d4  = idx & 7;
            const int wy = row / WIN, wx = row - wy * WIN;
            const int gy = oy - PADR + wy, gx = ox - PADR + wx;
            float4 kv = make_float4(0.f, 0.f, 0.f, 0.f);
            float4 vv = make_float4(0.f, 0.f, 0.f, 0.f);
            if (gy >= 0 && gy < HH && gx >= 0 && gx < WW) {
                const float* p = qkv + (size_t)(((b * HH + gy) * WW) + gx) * QKV_N
                               + head * HD + d4 * 4;
                kv = *(const float4*)(p + 256);
                vv = *(const float4*)(p + 512);
            }
            *(float4*)&ks_[row * KP + d4 * 4] = kv;
            *(float4*)&vs_[row * KP + d4 * 4] = vv;
        }
    }

    const int qi = tid >> 2;
    const int g  = tid & 3;
    const int qy = qi >> 3, qx = qi & 7;
    const size_t qpix = (size_t)((b * HH + oy + qy) * WW) + ox + qx;
    const float4* qp = (const float4*)(qkv + qpix * QKV_N + head * HD);
    float4 qv[8];
    #pragma unroll
    for (int cc = 0; cc < 8; ++cc) qv[cc] = qp[cc];

    __syncthreads();

    float sv[13];
    #pragma unroll
    for (int u = 0; u < 13; ++u) {
        const int j = g + 4 * u;
        const bool act = (j < 49);
        const int jc = act ? j : 48;
        const int di = jc / 7, dj = jc - di * 7;
        const float4* kr = (const float4*)(ks_ + ((qy + di) * WIN + qx + dj) * KP);
        float s0 = 0.f, s1 = 0.f, s2 = 0.f, s3 = 0.f;
        #pragma unroll
        for (int cc = 0; cc < 8; cc += 2) {
            const float4 k0 = kr[cc], k1 = kr[cc + 1];
            s0 = fmaf(qv[cc].x, k0.x, s0);
            s1 = fmaf(qv[cc].y, k0.y, s1);
            s2 = fmaf(qv[cc].z, k0.z, s2);
            s3 = fmaf(qv[cc].w, k0.w, s3);
            s0 = fmaf(qv[cc+1].x, k1.x, s0);
            s1 = fmaf(qv[cc+1].y, k1.y, s1);
            s2 = fmaf(qv[cc+1].z, k1.z, s2);
            s3 = fmaf(qv[cc+1].w, k1.w, s3);
        }
        sv[u] = act ? ((s0 + s1) + (s2 + s3) + rpbs[jc]) : -1e30f;
    }

    float m = sv[0];
    #pragma unroll
    for (int u = 1; u < 13; ++u) m = fmaxf(m, sv[u]);
    m = fmaxf(m, __shfl_xor_sync(0xffffffffu, m, 1));
    m = fmaxf(m, __shfl_xor_sync(0xffffffffu, m, 2));
    float ssum = 0.f;
    #pragma unroll
    for (int u = 0; u < 13; ++u) {
        const float e = __expf(sv[u] - m);
        sv[u] = e;
        ssum += e;
    }
    ssum += __shfl_xor_sync(0xffffffffu, ssum, 1);
    ssum += __shfl_xor_sync(0xffffffffu, ssum, 2);
    const float inv = 1.f / ssum;
    #pragma unroll
    for (int u = 0; u < 13; ++u) sv[u] *= inv;

    const int lanebase = (tid & 31) & ~3;
    float4 a0 = make_float4(0.f, 0.f, 0.f, 0.f);
    float4 a1 = make_float4(0.f, 0.f, 0.f, 0.f);
    #pragma unroll
    for (int di = 0; di < 7; ++di) {
        const float* vrow = vs_ + ((qy + di) * WIN + qx) * KP + g * 8;
        #pragma unroll
        for (int dj = 0; dj < 7; ++dj) {
            const int j = di * 7 + dj;
            const float w = __shfl_sync(0xffffffffu, sv[j >> 2],
                                        lanebase | (j & 3));
            const float4 v0 = *(const float4*)(vrow + dj * KP);
            const float4 v1 = *(const float4*)(vrow + dj * KP + 4);
            a0.x = fmaf(w, v0.x, a0.x); a0.y = fmaf(w, v0.y, a0.y);
            a0.z = fmaf(w, v0.z, a0.z); a0.w = fmaf(w, v0.w, a0.w);
            a1.x = fmaf(w, v1.x, a1.x); a1.y = fmaf(w, v1.y, a1.y);
            a1.z = fmaf(w, v1.z, a1.z); a1.w = fmaf(w, v1.w, a1.w);
        }
    }
    // transposed, tf32-rounded output: row c = head*32 + g*8 + u, col = qpix
    float* op = outT + (size_t)(head * HD + g * 8) * M_TOTAL + qpix;
    op[0 * M_TOTAL] = __uint_as_float(f2tf32(a0.x));
    op[1 * M_TOTAL] = __uint_as_float(f2tf32(a0.y));
    op[2 * M_TOTAL] = __uint_as_float(f2tf32(a0.z));
    op[3 * M_TOTAL] = __uint_as_float(f2tf32(a0.w));
    op[4 * M_TOTAL] = __uint_as_float(f2tf32(a1.x));
    op[5 * M_TOTAL] = __uint_as_float(f2tf32(a1.y));
    op[6 * M_TOTAL] = __uint_as_float(f2tf32(a1.z));
    op[7 * M_TOTAL] = __uint_as_float(f2tf32(a1.w));
}

// ---------------------------------------------------------------------------
extern "C" void kernel_launch(void* const* d_in, const int* in_sizes, int n_in,
                              void* d_out, int out_size)
{
    (void)in_sizes; (void)n_in; (void)out_size;
    const float* x      = (const float*)d_in[0];
    const float* w_qkv  = (const float*)d_in[1];
    const float* b_qkv  = (const float*)d_in[2];
    const float* rpb    = (const float*)d_in[3];
    const float* w_proj = (const float*)d_in[4];
    const float* b_proj = (const float*)d_in[5];
    float* out = (float*)d_out;

    float *qkvb = nullptr, *attnT = nullptr, *xt = nullptr, *wq = nullptr, *wp = nullptr;
    cudaGetSymbolAddress((void**)&qkvb, g_qkv);
    cudaGetSymbolAddress((void**)&attnT, g_attnT);
    cudaGetSymbolAddress((void**)&xt, g_xt);
    cudaGetSymbolAddress((void**)&wq, g_wq);
    cudaGetSymbolAddress((void**)&wp, g_wp);

    cudaFuncSetAttribute(tgemm_ca, cudaFuncAttributeMaxDynamicSharedMemorySize,
                         GEMM_SMEM);
    cudaFuncSetAttribute(na2d_attn, cudaFuncAttributeMaxDynamicSharedMemorySize,
                         ATTN_SMEM_BYTES);

    const float qscale = 0.17677669529663689f; // 32^-0.5

    // 0) prep: transpose+round x -> [C][M]; round weights ([K][N] kept)
    transpose_round_x<<<dim3(M_TOTAL / 32, CC / 32), dim3(32, 8)>>>(x, xt);
    {
        const int nq = CC * QKV_N / 4;
        tf32_round_kernel<<<(nq + 255) / 256, 256>>>((const float4*)w_qkv, (float4*)wq, nq);
        const int np = CC * CC / 4;
        tf32_round_kernel<<<(np + 255) / 256, 256>>>((const float4*)w_proj, (float4*)wp, np);
    }

    // 1) qkv = x @ w_qkv + b_qkv  (q columns pre-scaled)
    tgemm_ca<<<dim3(QKV_N / 64, M_TOTAL / 128), 256, GEMM_SMEM>>>(
        xt, wq, b_qkv, qkvb, M_TOTAL, QKV_N, 256, qscale);

    // 2) neighborhood attention (writes transposed tf32 output)
    na2d_attn<<<dim3(49, NHEAD, BATCH), 256, ATTN_SMEM_BYTES>>>(qkvb, rpb, attnT);

    // 3) out = attn @ w_proj + b_proj
    tgemm_ca<<<dim3(CC / 64, M_TOTAL / 128), 256, GEMM_SMEM>>>(
        attnT, wp, b_proj, out, M_TOTAL, CC, 0, 1.f);
}